// round 17
// baseline (speedup 1.0000x reference)
#include <cuda_runtime.h>
#include <cuda_bf16.h>
#include <math.h>
#include <stdint.h>

#define NB 4096
#define FEATN 30

// ---------------- scratch (static device globals; no allocation) ----------------
__device__ float g_fvs[NB * FEATN];
__device__ float g_fvd[NB * FEATN];
__device__ float g_fps[NB * FEATN];
__device__ float g_fpd[NB * FEATN];
__device__ float g_y30[NB * FEATN];
__device__ __align__(16) unsigned char g_w2t[10 * 4096];

// ---------------- warp-MMA helpers ----------------
__device__ __forceinline__ uint32_t smem_u32(const void* p) {
    uint32_t a;
    asm("{ .reg .u64 t; cvta.to.shared.u64 t, %1; cvt.u32.u64 %0, t; }" : "=r"(a) : "l"(p));
    return a;
}
__device__ __forceinline__ uint32_t sw128(uint32_t o) { return o ^ ((o >> 3) & 0x70); }

__device__ __forceinline__ void ldmx4(uint32_t* r, uint32_t addr) {
    asm volatile("ldmatrix.sync.aligned.m8n8.x4.shared.b16 {%0,%1,%2,%3}, [%4];"
                 : "=r"(r[0]), "=r"(r[1]), "=r"(r[2]), "=r"(r[3]) : "r"(addr));
}
__device__ __forceinline__ void ldmx2(uint32_t* r, uint32_t addr) {
    asm volatile("ldmatrix.sync.aligned.m8n8.x2.shared.b16 {%0,%1}, [%2];"
                 : "=r"(r[0]), "=r"(r[1]) : "r"(addr));
}
__device__ __forceinline__ void mma16816(float* d, const uint32_t* a, const uint32_t* b) {
    asm volatile("mma.sync.aligned.m16n8k16.row.col.f32.bf16.bf16.f32 "
                 "{%0,%1,%2,%3}, {%4,%5,%6,%7}, {%8,%9}, {%0,%1,%2,%3};"
                 : "+f"(d[0]), "+f"(d[1]), "+f"(d[2]), "+f"(d[3])
                 : "r"(a[0]), "r"(a[1]), "r"(a[2]), "r"(a[3]), "r"(b[0]), "r"(b[1]));
}
__device__ __forceinline__ void bf16hl(float v, uint32_t& h, uint32_t& l) {
    __nv_bfloat16 vh = __float2bfloat16(v);
    __nv_bfloat16 vl = __float2bfloat16(v - __bfloat162float(vh));
    h = (uint32_t)*reinterpret_cast<uint16_t*>(&vh);
    l = (uint32_t)*reinterpret_cast<uint16_t*>(&vl);
}

// =======================================================================
// Prep: bf16 hi/lo SW128 tile images of conv2 weights.
// =======================================================================
__global__ void prep_w2t(const float* __restrict__ W2) {
    int i = blockIdx.x * 256 + threadIdx.x;
    if (i < 20480) {
        int tile = i >> 11;
        int rem  = i & 2047;
        int n = rem >> 6, c = rem & 63;
        int half = tile / 5, k = tile % 5;
        float w = (n < 30) ? W2[n * 320 + c * 5 + k] : 0.f;
        __nv_bfloat16 wh = __float2bfloat16(w);
        __nv_bfloat16 val = half ? __float2bfloat16(w - __bfloat162float(wh)) : wh;
        *reinterpret_cast<__nv_bfloat16*>(
            g_w2t + tile * 4096 + sw128((uint32_t)(n * 128 + c * 2))) = val;
    }
}

// =======================================================================
// Encode kernel (unchanged from R13, passing): im2col GEMM via mma.sync.
// =======================================================================
#define E2_XH    0u
#define E2_XL    32768u
#define E2_W     65536u
#define E2_PART  69632u
#define E2_BC    71680u
#define E2_HSH   71936u
#define ENC_SMEM 72192

__global__ __launch_bounds__(256, 3) void encode_kernel(
    const float* __restrict__ S_V, const float* __restrict__ S_P,
    const float* __restrict__ Wc_v, const float* __restrict__ bc_v,
    const float* __restrict__ Ws_v, const float* __restrict__ bs_v,
    const float* __restrict__ Wd_v, const float* __restrict__ bd_v,
    const float* __restrict__ Wc_p, const float* __restrict__ bc_p,
    const float* __restrict__ Ws_p, const float* __restrict__ bs_p,
    const float* __restrict__ Wd_p, const float* __restrict__ bd_p)
{
    extern __shared__ __align__(16) unsigned char smraw[];
    const uint32_t smb = smem_u32(smraw);

    const int tid  = threadIdx.x;
    const int b    = blockIdx.x;
    const int mo   = blockIdx.y;
    const int lane = tid & 31;
    const int wid  = tid >> 5;

    float* part = (float*)(smraw + E2_PART);
    float* bcs  = (float*)(smraw + E2_BC);
    float* hsh  = (float*)(smraw + E2_HSH);

    {
        const float* Sb = (mo ? S_P : S_V) + (size_t)b * 3072;
        for (int r = tid; r < 1024; r += 256) {
            uint4 h0 = make_uint4(0, 0, 0, 0), h1 = h0, l0 = h0, l1 = h0;
            if (r <= 1021) {
                uint32_t hh[9], ll[9];
#pragma unroll
                for (int i = 0; i < 9; i++) bf16hl(Sb[3 * r + i], hh[i], ll[i]);
                h0.x = hh[0] | (hh[1] << 16); h0.y = hh[2] | (hh[3] << 16);
                h0.z = hh[4] | (hh[5] << 16); h0.w = hh[6] | (hh[7] << 16);
                h1.x = hh[8];
                l0.x = ll[0] | (ll[1] << 16); l0.y = ll[2] | (ll[3] << 16);
                l0.z = ll[4] | (ll[5] << 16); l0.w = ll[6] | (ll[7] << 16);
                l1.x = ll[8];
            }
            *reinterpret_cast<uint4*>(smraw + E2_XH + r * 32)      = h0;
            *reinterpret_cast<uint4*>(smraw + E2_XH + r * 32 + 16) = h1;
            *reinterpret_cast<uint4*>(smraw + E2_XL + r * 32)      = l0;
            *reinterpret_cast<uint4*>(smraw + E2_XL + r * 32 + 16) = l1;
        }
    }
    {
        if (tid < 128) {
            const uint32_t base = E2_W + (uint32_t)(tid >> 6) * 2048u +
                                  (uint32_t)(tid & 63) * 32u;
            *reinterpret_cast<uint16_t*>(smraw + base + 18) = 0;
            *reinterpret_cast<uint32_t*>(smraw + base + 20) = 0;
            *reinterpret_cast<uint32_t*>(smraw + base + 24) = 0;
            *reinterpret_cast<uint32_t*>(smraw + base + 28) = 0;
        }
        const float* Wc = mo ? Wc_p : Wc_v;
        for (int i = tid; i < 576; i += 256) {
            const int o = i / 9, j = i - o * 9;
            const int c = j / 3, k = j - c * 3;
            const int jj = k * 3 + c;
            uint32_t wh, wl;
            bf16hl(Wc[i], wh, wl);
            *reinterpret_cast<uint16_t*>(smraw + E2_W + o * 32 + jj * 2) = (uint16_t)wh;
            *reinterpret_cast<uint16_t*>(smraw + E2_W + 2048 + o * 32 + jj * 2) = (uint16_t)wl;
        }
        if (tid < 64) bcs[tid] = (mo ? bc_p : bc_v)[tid];
    }
    __syncthreads();

    uint32_t bhf[8][2], blf[8][2];
#pragma unroll
    for (int nt = 0; nt < 8; nt++) {
        const uint32_t baddr = smb + E2_W +
            (uint32_t)(nt * 8 + (lane & 7)) * 32 + (uint32_t)((lane >> 3) & 1) * 16;
        ldmx2(bhf[nt], baddr);
        ldmx2(blf[nt], baddr + 2048);
    }

    float s0[8], s1[8];
#pragma unroll
    for (int nt = 0; nt < 8; nt++) { s0[nt] = 0.f; s1[nt] = 0.f; }

#pragma unroll
    for (int mt = 0; mt < 8; mt++) {
        const int R = (wid * 8 + mt) * 16;
        const uint32_t ao = smb + E2_XH +
            (uint32_t)(R + (lane & 15)) * 32 + (uint32_t)(lane >> 4) * 16;
        uint32_t Ah[4], Al[4];
        ldmx4(Ah, ao);
        ldmx4(Al, ao + 32768u);
        const bool r1ok = (R + 8 + (lane >> 2)) < 1022;
#pragma unroll
        for (int nt = 0; nt < 8; nt++) {
            float d[4] = {0.f, 0.f, 0.f, 0.f};
            mma16816(d, Ah, bhf[nt]);
            mma16816(d, Al, bhf[nt]);
            mma16816(d, Ah, blf[nt]);
            const int o = nt * 8 + (lane & 3) * 2;
            const float bias0 = bcs[o], bias1 = bcs[o + 1];
            s0[nt] += fmaxf(d[0] + bias0, 0.f);
            s1[nt] += fmaxf(d[1] + bias1, 0.f);
            if (r1ok) {
                s0[nt] += fmaxf(d[2] + bias0, 0.f);
                s1[nt] += fmaxf(d[3] + bias1, 0.f);
            }
        }
    }

#pragma unroll
    for (int nt = 0; nt < 8; nt++) {
#pragma unroll
        for (int off = 4; off <= 16; off <<= 1) {
            s0[nt] += __shfl_xor_sync(0xffffffffu, s0[nt], off);
            s1[nt] += __shfl_xor_sync(0xffffffffu, s1[nt], off);
        }
    }
    if (lane < 4) {
#pragma unroll
        for (int nt = 0; nt < 8; nt++) {
            const int o = nt * 8 + lane * 2;
            part[wid * 64 + o]     = s0[nt];
            part[wid * 64 + o + 1] = s1[nt];
        }
    }
    __syncthreads();

    if (tid < 64) {
        float s = 0.f;
#pragma unroll
        for (int w = 0; w < 8; w++) s += part[w * 64 + tid];
        hsh[tid] = s * (1.f / 1022.f);
    }
    __syncthreads();

    if (tid < 60) {
        const int  j2 = tid % 30;
        const bool first = tid < 30;
        const float* Wm = first ? (mo ? Ws_p : Ws_v) : (mo ? Wd_p : Wd_v);
        const float* bm = first ? (mo ? bs_p : bs_v) : (mo ? bd_p : bd_v);
        float* outp = first ? (mo ? g_fps : g_fvs) : (mo ? g_fpd : g_fvd);
        float s = bm[j2];
        for (int i = 0; i < 64; i++) s = fmaf(hsh[i], Wm[i * 30 + j2], s);
        outp[b * 30 + j2] = s;
    }
}

// =======================================================================
// Physical-model kernel v3: BOTH convs as im2col MMA.
//   conv1: im2col row t = S[3t..3t+14] (col jj=k*3+c), M=1024,K=16,N=64;
//          maxpool4 via 2x shfl_xor in registers; +bias; bf16 hi/lo -> p1.
//   conv2: unchanged R10 scheme (shift in A row base, register accum).
// One block per sample, 512 threads, ~174 KB smem (1 CTA/SM).
// =======================================================================
#define PIM_H     0u          /* 32768: 1024 rows x 32B */
#define PIM_L     32768u
#define PWBUF     65536u      /* 40960 */
#define PP1H      106496u     /* 32768 */
#define PP1L      139264u
#define PW1B      172032u     /* 4096: hi 2048 + lo 2048 */
#define PPART     176128u     /* 480 floats */
#define PB1S      178048u     /* 64 floats */
#define PCO       0u          /* conv_out aliases PIM after conv1 */
#define PHYS_SMEM 178304
#define COSTR     33

__global__ __launch_bounds__(512, 1) void phys_kernel(
    const float* __restrict__ S_P1,
    const float* __restrict__ W1, const float* __restrict__ b1,
    const float* __restrict__ b2)
{
    extern __shared__ __align__(16) unsigned char smraw[];
    const uint32_t smb = smem_u32(smraw);
    float* part = (float*)(smraw + PPART);
    float* b1s  = (float*)(smraw + PB1S);

    const int tid  = threadIdx.x;
    const int b    = blockIdx.x;
    const int wid  = tid >> 5;
    const int lane = tid & 31;

    // ---------------- phase 0: fill im2col, weights, zero p1 row 255 --------
    {
        const float* Sb = S_P1 + (size_t)b * 3072;
        for (int r = tid; r < 1024; r += 512) {
            uint4 h0 = make_uint4(0, 0, 0, 0), h1 = h0, l0 = h0, l1 = h0;
            if (r <= 1019) {
                uint32_t hh[15], ll[15];
#pragma unroll
                for (int i = 0; i < 15; i++) bf16hl(Sb[3 * r + i], hh[i], ll[i]);
                h0.x = hh[0] | (hh[1] << 16);  h0.y = hh[2] | (hh[3] << 16);
                h0.z = hh[4] | (hh[5] << 16);  h0.w = hh[6] | (hh[7] << 16);
                h1.x = hh[8] | (hh[9] << 16);  h1.y = hh[10] | (hh[11] << 16);
                h1.z = hh[12] | (hh[13] << 16); h1.w = hh[14];
                l0.x = ll[0] | (ll[1] << 16);  l0.y = ll[2] | (ll[3] << 16);
                l0.z = ll[4] | (ll[5] << 16);  l0.w = ll[6] | (ll[7] << 16);
                l1.x = ll[8] | (ll[9] << 16);  l1.y = ll[10] | (ll[11] << 16);
                l1.z = ll[12] | (ll[13] << 16); l1.w = ll[14];
            }
            *reinterpret_cast<uint4*>(smraw + PIM_H + r * 32)      = h0;
            *reinterpret_cast<uint4*>(smraw + PIM_H + r * 32 + 16) = h1;
            *reinterpret_cast<uint4*>(smraw + PIM_L + r * 32)      = l0;
            *reinterpret_cast<uint4*>(smraw + PIM_L + r * 32 + 16) = l1;
        }
        // conv2 weight tiles
        const uint4* gw = (const uint4*)g_w2t;
        uint4* swp = (uint4*)(smraw + PWBUF);
        for (int i = tid; i < 2560; i += 512) swp[i] = gw[i];
        // conv1 weights: W1[o][c][k] -> col jj = k*3+c; col 15 zeroed
        if (tid < 128) {
            const uint32_t base = PW1B + (uint32_t)(tid >> 6) * 2048u +
                                  (uint32_t)(tid & 63) * 32u;
            *reinterpret_cast<uint16_t*>(smraw + base + 30) = 0;
        }
        for (int i = tid; i < 960; i += 512) {
            const int o = i / 15, j = i - o * 15;
            const int c = j / 5, k = j - c * 5;
            const int jj = k * 3 + c;
            uint32_t wh, wl;
            bf16hl(W1[i], wh, wl);
            *reinterpret_cast<uint16_t*>(smraw + PW1B + o * 32 + jj * 2) = (uint16_t)wh;
            *reinterpret_cast<uint16_t*>(smraw + PW1B + 2048 + o * 32 + jj * 2) = (uint16_t)wl;
        }
        if (tid < 64) b1s[tid] = b1[tid];
        // zero p1 row 255
        if (tid < 32) {
            const uint32_t off = sw128((uint32_t)(255 * 128 + tid * 4));
            *reinterpret_cast<uint32_t*>(smraw + PP1H + off) = 0u;
            *reinterpret_cast<uint32_t*>(smraw + PP1L + off) = 0u;
        }
    }
    __syncthreads();

    // ---------------- phase 1: conv1 MMA + register maxpool4 -> p1 ----------
    {
        uint32_t bhf[8][2], blf[8][2];
#pragma unroll
        for (int nt = 0; nt < 8; nt++) {
            const uint32_t baddr = smb + PW1B +
                (uint32_t)(nt * 8 + (lane & 7)) * 32 + (uint32_t)((lane >> 3) & 1) * 16;
            ldmx2(bhf[nt], baddr);
            ldmx2(blf[nt], baddr + 2048);
        }
        const bool writer = (lane & 12) == 0;        // lanes 0-3, 16-19
        const int  wsel   = (lane >> 4) & 1;         // 0: windows +0/+2, 1: +1/+3

#pragma unroll
        for (int mt = 0; mt < 4; mt++) {
            const int R = (wid * 4 + mt) * 16;       // conv rows R..R+15
            const uint32_t ao = smb + PIM_H +
                (uint32_t)(R + (lane & 15)) * 32 + (uint32_t)(lane >> 4) * 16;
            uint32_t Ah[4], Al[4];
            ldmx4(Ah, ao);
            ldmx4(Al, ao + 32768u);
#pragma unroll
            for (int nt = 0; nt < 8; nt++) {
                float d[4] = {0.f, 0.f, 0.f, 0.f};
                mma16816(d, Ah, bhf[nt]);
                mma16816(d, Al, bhf[nt]);
                mma16816(d, Ah, blf[nt]);
                // maxpool4 across rows: lane bits 2,3
                float v0 = d[0], v1 = d[1], v2 = d[2], v3 = d[3];
                v0 = fmaxf(v0, __shfl_xor_sync(0xffffffffu, v0, 4));
                v0 = fmaxf(v0, __shfl_xor_sync(0xffffffffu, v0, 8));
                v1 = fmaxf(v1, __shfl_xor_sync(0xffffffffu, v1, 4));
                v1 = fmaxf(v1, __shfl_xor_sync(0xffffffffu, v1, 8));
                v2 = fmaxf(v2, __shfl_xor_sync(0xffffffffu, v2, 4));
                v2 = fmaxf(v2, __shfl_xor_sync(0xffffffffu, v2, 8));
                v3 = fmaxf(v3, __shfl_xor_sync(0xffffffffu, v3, 4));
                v3 = fmaxf(v3, __shfl_xor_sync(0xffffffffu, v3, 8));
                if (writer) {
                    const int o  = nt * 8 + (lane & 3) * 2;
                    const float bo0 = b1s[o], bo1 = b1s[o + 1];
                    const int j01 = (R >> 2) + wsel;       // v0,v1 window
                    const int j23 = j01 + 2;               // v2,v3 window
                    {
                        uint32_t h0, l0v, h1v, l1v;
                        bf16hl(v0 + bo0, h0, l0v);
                        bf16hl(v1 + bo1, h1v, l1v);
                        const uint32_t off = sw128((uint32_t)(j01 * 128 + o * 2));
                        *reinterpret_cast<uint32_t*>(smraw + PP1H + off) = h0 | (h1v << 16);
                        *reinterpret_cast<uint32_t*>(smraw + PP1L + off) = l0v | (l1v << 16);
                    }
                    if (j23 < 255) {
                        uint32_t h0, l0v, h1v, l1v;
                        bf16hl(v2 + bo0, h0, l0v);
                        bf16hl(v3 + bo1, h1v, l1v);
                        const uint32_t off = sw128((uint32_t)(j23 * 128 + o * 2));
                        *reinterpret_cast<uint32_t*>(smraw + PP1H + off) = h0 | (h1v << 16);
                        *reinterpret_cast<uint32_t*>(smraw + PP1L + off) = l0v | (l1v << 16);
                    }
                }
            }
        }
    }
    __syncthreads();

    // ---------------- phase 2: conv2 MMA (R10 scheme, new offsets) ----------
    {
        const uint32_t a_rowl = (uint32_t)(lane & 15);
        const uint32_t a_koff = (uint32_t)((lane >> 4) * 16);
        const uint32_t bn     = (uint32_t)(lane & 7) * 128;
        const uint32_t bkoff  = (uint32_t)((lane >> 3) & 1) * 16;

        float d[4][4];
#pragma unroll
        for (int nt = 0; nt < 4; nt++)
#pragma unroll
            for (int i = 0; i < 4; i++) d[nt][i] = 0.f;

#pragma unroll
        for (int k = 0; k < 5; k++) {
            const uint32_t bbase_h = smb + PWBUF + (uint32_t)k * 4096;
            const uint32_t bbase_l = bbase_h + 5u * 4096;
            const uint32_t arow    = (uint32_t)(wid * 16 + k) + a_rowl;
#pragma unroll
            for (int ks = 0; ks < 4; ks++) {
                uint32_t Ah[4], Al[4];
                const uint32_t ao = sw128(arow * 128 + (uint32_t)ks * 32 + a_koff);
                ldmx4(Ah, smb + PP1H + ao);
                ldmx4(Al, smb + PP1L + ao);
#pragma unroll
                for (int nt = 0; nt < 4; nt++) {
                    const uint32_t bo =
                        sw128(bn + (uint32_t)nt * 1024 + (uint32_t)ks * 32 + bkoff);
                    uint32_t bh[2], bl[2];
                    ldmx2(bh, bbase_h + bo);
                    ldmx2(bl, bbase_l + bo);
                    mma16816(d[nt], Ah, bh);
                    mma16816(d[nt], Al, bh);
                    mma16816(d[nt], Ah, bl);
                }
            }
        }
        __syncthreads();   // im2col reads done long ago; conv_out aliases PIM

        {
            float* conv_out = (float*)(smraw + PCO);
            const int t0 = wid * 16 + (lane >> 2);
            const int t1 = t0 + 8;
            const int n0 = (lane & 3) * 2;
#pragma unroll
            for (int nt = 0; nt < 4; nt++) {
                const int n = nt * 8 + n0;
                if (t0 < 248) {
                    conv_out[t0 * COSTR + n]     = d[nt][0];
                    conv_out[t0 * COSTR + n + 1] = d[nt][1];
                }
                if (t1 < 248) {
                    conv_out[t1 * COSTR + n]     = d[nt][2];
                    conv_out[t1 * COSTR + n + 1] = d[nt][3];
                }
            }
        }
    }
    __syncthreads();

    // ---------------- phase 3: maxpool4 + mean -> y30 -----------------------
    {
        float* conv_out = (float*)(smraw + PCO);
        if (tid < 480) {
            const int n = tid >> 4, jg = tid & 15;
            float s = 0.f;
#pragma unroll
            for (int j = jg; j < 62; j += 16) {
                const float* cr = conv_out + 4 * j * COSTR + n;
                float mx = fmaxf(fmaxf(cr[0], cr[COSTR]),
                                 fmaxf(cr[2 * COSTR], cr[3 * COSTR]));
                s += mx;
            }
            part[n * 16 + jg] = s;
        }
    }
    __syncthreads();
    if (tid < 30) {
        float s = 0.f;
#pragma unroll
        for (int g = 0; g < 16; g++) s += part[tid * 16 + g];
        g_y30[b * 30 + tid] = s * (1.f / 62.f) + b2[tid];
    }
}

// =======================================================================
// Fusion kernel (unchanged).
// =======================================================================
__global__ __launch_bounds__(256) void fuse_kernel(
    const int* __restrict__ pairs,
    const float* __restrict__ Wsp, const float* __restrict__ bsp,
    const float* __restrict__ Wa, const float* __restrict__ ba,
    const float* __restrict__ Wf, const float* __restrict__ bf,
    float* __restrict__ out)
{
    __shared__ float Wsp_s[900], bsp_s[30], Wa_s[5760], ba_s[192], Wf_s[128], bf_s[4];
    __shared__ float ain[8][4][32];

    const int tid = threadIdx.x;
    for (int i = tid; i < 900; i += 256) Wsp_s[i] = Wsp[i];
    for (int i = tid; i < 5760; i += 256) Wa_s[i] = Wa[i];
    if (tid < 30)  bsp_s[tid] = bsp[tid];
    if (tid < 192) ba_s[tid]  = ba[tid];
    if (tid < 128) Wf_s[tid]  = Wf[tid];
    if (tid < 4)   bf_s[tid]  = bf[tid];
    __syncthreads();

    const int warp = tid >> 5, lane = tid & 31;
    const int b = blockIdx.x * 8 + warp;

    float fvs = 0.f, fps = 0.f, fvd = 0.f, fpd = 0.f, yv = 0.f;
    if (lane < 30) {
        fvs = g_fvs[b * 30 + lane];
        fps = g_fps[b * 30 + lane];
        fvd = g_fvd[b * 30 + lane];
        fpd = g_fpd[b * 30 + lane];
        yv  = g_y30[b * 30 + lane];
    }

    float h1 = (lane < 30) ? bsp_s[lane] : 0.f;
    float h2 = h1;
    for (int i = 0; i < 30; i++) {
        float av = __shfl_sync(0xffffffffu, fvs, i);
        float bv = __shfl_sync(0xffffffffu, fps, i);
        float wv = (lane < 30) ? Wsp_s[i * 30 + lane] : 0.f;
        h1 = fmaf(av, wv, h1);
        h2 = fmaf(bv, wv, h2);
    }

    const int   pr = pairs[b];
    const float pf = (float)pr;
    const float h12 = h1 + h2;
    float m1 = fmaxf(h12, fmaxf(h1, h2));
    float lse1 = m1 + logf(2.f * expf(h12 - m1) + expf(h1 - m1) + expf(h2 - m1));
    float m2 = fmaxf(0.f, fmaxf(h1, h2));
    float lse2 = m2 + logf(2.f * expf(0.f - m2) + expf(h1 - m2) + expf(h2 - m2));
    const float favg = pf * (lse1 - lse2) + (1.f - pf) * h2;

    if (lane < 30) {
        ain[warp][0][lane] = fpd;
        ain[warp][1][lane] = favg;
        ain[warp][2][lane] = yv;
        ain[warp][3][lane] = fvd;
    }
    __syncwarp();

    float r[4][6];
#pragma unroll
    for (int g = 0; g < 6; g++) {
        float s0 = ba_s[g * 32 + lane], s1 = s0, s2 = s0, s3 = s0;
        for (int i = 0; i < 30; i++) {
            const float wv = Wa_s[i * 192 + g * 32 + lane];
            s0 = fmaf(ain[warp][0][i], wv, s0);
            s1 = fmaf(ain[warp][1][i], wv, s1);
            s2 = fmaf(ain[warp][2][i], wv, s2);
            s3 = fmaf(ain[warp][3][i], wv, s3);
        }
        r[0][g] = s0; r[1][g] = s1; r[2][g] = s2; r[3][g] = s3;
    }

    const float qsum3 = r[0][0] + r[1][0] + r[2][0];
    const float qm = pf * 0.25f * (qsum3 + r[3][0]) + (1.f - pf) * (qsum3 * (1.f / 3.f));

    float lg[4][4];
#pragma unroll
    for (int n = 0; n < 4; n++) {
#pragma unroll
        for (int t = 0; t < 4; t++) {
            float p = r[t][2 + n] * qm;
#pragma unroll
            for (int off = 16; off; off >>= 1) p += __shfl_xor_sync(0xffffffffu, p, off);
            lg[n][t] = p * 0.17677669529663687f;
        }
    }

#pragma unroll
    for (int n = 0; n < 4; n++) {
        const float l0 = lg[n][0], l1 = lg[n][1], l2 = lg[n][2], l3 = lg[n][3];
        float m = fmaxf(fmaxf(l0, l1), l2);
        if (pr) m = fmaxf(m, l3);
        const float e0 = expf(l0 - m), e1 = expf(l1 - m), e2 = expf(l2 - m);
        const float e3 = pr ? expf(l3 - m) : 0.f;
        const float inv = 1.f / (e0 + e1 + e2 + e3);
        const float ff = (e0 * r[0][1] + e1 * r[1][1] + e2 * r[2][1] + e3 * r[3][1]) * inv;
        float p = ff * Wf_s[lane * 4 + n];
#pragma unroll
        for (int off = 16; off; off >>= 1) p += __shfl_xor_sync(0xffffffffu, p, off);
        if (lane == 0) out[b * 4 + n] = p + bf_s[n];
    }
}

// =======================================================================
extern "C" void kernel_launch(void* const* d_in, const int* in_sizes, int n_in,
                              void* d_out, int out_size)
{
    (void)in_sizes; (void)n_in; (void)out_size;
    const int*   pairs = (const int*)d_in[0];
    const float* S_V  = (const float*)d_in[1];
    const float* S_P  = (const float*)d_in[2];
    const float* S_P1 = (const float*)d_in[3];
    const float* Wc_v = (const float*)d_in[4];  const float* bc_v = (const float*)d_in[5];
    const float* Ws_v = (const float*)d_in[6];  const float* bs_v = (const float*)d_in[7];
    const float* Wd_v = (const float*)d_in[8];  const float* bd_v = (const float*)d_in[9];
    const float* Wc_p = (const float*)d_in[10]; const float* bc_p = (const float*)d_in[11];
    const float* Ws_p = (const float*)d_in[12]; const float* bs_p = (const float*)d_in[13];
    const float* Wd_p = (const float*)d_in[14]; const float* bd_p = (const float*)d_in[15];
    const float* Wsp  = (const float*)d_in[16]; const float* bsp  = (const float*)d_in[17];
    const float* W1   = (const float*)d_in[18]; const float* b1   = (const float*)d_in[19];
    const float* W2   = (const float*)d_in[20]; const float* b2   = (const float*)d_in[21];
    const float* Wa   = (const float*)d_in[22]; const float* ba   = (const float*)d_in[23];
    const float* Wf   = (const float*)d_in[24]; const float* bf   = (const float*)d_in[25];
    float* out = (float*)d_out;

    cudaFuncSetAttribute(phys_kernel, cudaFuncAttributeMaxDynamicSharedMemorySize,
                         PHYS_SMEM);
    cudaFuncSetAttribute(encode_kernel, cudaFuncAttributeMaxDynamicSharedMemorySize,
                         ENC_SMEM);

    prep_w2t<<<80, 256>>>(W2);
    encode_kernel<<<dim3(NB, 2), 256, ENC_SMEM>>>(S_V, S_P,
                                        Wc_v, bc_v, Ws_v, bs_v, Wd_v, bd_v,
                                        Wc_p, bc_p, Ws_p, bs_p, Wd_p, bd_p);
    phys_kernel<<<NB, 512, PHYS_SMEM>>>(S_P1, W1, b1, b2);
    fuse_kernel<<<NB / 8, 256>>>(pairs, Wsp, bsp, Wa, ba, Wf, bf, out);
}